// round 1
// baseline (speedup 1.0000x reference)
#include <cuda_runtime.h>
#include <cuda_bf16.h>
#include <cstdint>

using bf16  = __nv_bfloat16;
using bf162 = __nv_bfloat162;

// ---------------- problem constants ----------------
static constexpr int  Bb = 32, Cc = 512, Nn = 1024, C3 = 1536;

// ---------------- device scratch (no allocs allowed) ----------------
__device__ __align__(16) float g_ga[Bb * Cc];
__device__ __align__(16) float g_gb[Bb * Cc];
__device__ __align__(16) bf16  g_w1b[C3 * Cc];
__device__ __align__(16) bf16  g_w2t[Cc * Cc];
__device__ __align__(16) bf16  g_xn  [(size_t)Bb * Cc * Nn];
__device__ __align__(16) bf16  g_qkv [(size_t)Bb * C3 * Nn];
__device__ __align__(16) bf16  g_qt  [(size_t)Bb * Nn * Cc];
__device__ __align__(16) bf16  g_vt  [(size_t)Bb * Nn * Cc];
__device__ __align__(16) float g_S   [(size_t)Bb * Nn * Nn];
__device__ __align__(16) bf16  g_P   [(size_t)Bb * Nn * Nn];
__device__ __align__(16) bf16  g_attn[(size_t)Bb * Nn * Cc];
__device__ __align__(16) float g_oT  [(size_t)Bb * Nn * Cc];

// ---------------- small PTX helpers ----------------
__device__ __forceinline__ uint32_t smem_u32(const void* p) {
    return (uint32_t)__cvta_generic_to_shared(p);
}
__device__ __forceinline__ void cp_async16(uint32_t s, const void* g) {
    asm volatile("cp.async.cg.shared.global [%0], [%1], 16;\n" :: "r"(s), "l"(g));
}
__device__ __forceinline__ void cp_commit() {
    asm volatile("cp.async.commit_group;\n" ::: "memory");
}
__device__ __forceinline__ void cp_wait0() {
    asm volatile("cp.async.wait_group 0;\n" ::: "memory");
}
__device__ __forceinline__ void ldsm_x4(uint32_t* r, uint32_t addr) {
    asm volatile("ldmatrix.sync.aligned.m8n8.x4.shared.b16 {%0,%1,%2,%3}, [%4];\n"
                 : "=r"(r[0]), "=r"(r[1]), "=r"(r[2]), "=r"(r[3]) : "r"(addr));
}
__device__ __forceinline__ void ldsm_x4_t(uint32_t* r, uint32_t addr) {
    asm volatile("ldmatrix.sync.aligned.m8n8.x4.trans.shared.b16 {%0,%1,%2,%3}, [%4];\n"
                 : "=r"(r[0]), "=r"(r[1]), "=r"(r[2]), "=r"(r[3]) : "r"(addr));
}
__device__ __forceinline__ void mma_16816(float* d, const uint32_t* a, const uint32_t* b) {
    asm volatile("mma.sync.aligned.m16n8k16.row.col.f32.bf16.bf16.f32 "
                 "{%0,%1,%2,%3}, {%4,%5,%6,%7}, {%8,%9}, {%0,%1,%2,%3};\n"
                 : "+f"(d[0]), "+f"(d[1]), "+f"(d[2]), "+f"(d[3])
                 : "r"(a[0]), "r"(a[1]), "r"(a[2]), "r"(a[3]), "r"(b[0]), "r"(b[1]));
}

// ---------------- stage 1: weight convert (w2 transposed) ----------------
__global__ void wconv_kernel(const float* __restrict__ w1, const float* __restrict__ w2,
                             bf16* __restrict__ w1b, bf16* __restrict__ w2t) {
    int i = blockIdx.x * 256 + threadIdx.x;
    if (i < C3 * Cc) w1b[i] = __float2bfloat16(w1[i]);
    if (i < Cc * Cc) {
        int o = i >> 9, c = i & 511;
        w2t[c * Cc + o] = __float2bfloat16(w2[i]);
    }
}

// ---------------- stage 2: groupnorm stats -> per-(b,c) affine ----------------
__global__ __launch_bounds__(256) void gn_stats_kernel(
        const float* __restrict__ x, const float* __restrict__ gns,
        const float* __restrict__ gnb, float* __restrict__ ga, float* __restrict__ gb) {
    int bg = blockIdx.x;  // b*32+g, group = 16 channels * 1024 = 16384 contiguous floats
    const float4* p = reinterpret_cast<const float4*>(x) + (size_t)bg * 4096;
    float s = 0.f, ss = 0.f;
    for (int i = threadIdx.x; i < 4096; i += 256) {
        float4 v = p[i];
        s  += v.x + v.y + v.z + v.w;
        ss += v.x * v.x + v.y * v.y + v.z * v.z + v.w * v.w;
    }
    __shared__ float sh[34];
    #pragma unroll
    for (int o = 16; o > 0; o >>= 1) {
        s  += __shfl_xor_sync(~0u, s, o);
        ss += __shfl_xor_sync(~0u, ss, o);
    }
    int w = threadIdx.x >> 5;
    if ((threadIdx.x & 31) == 0) { sh[w] = s; sh[w + 8] = ss; }
    __syncthreads();
    if (threadIdx.x == 0) {
        float ts = 0.f, tss = 0.f;
        #pragma unroll
        for (int i = 0; i < 8; ++i) { ts += sh[i]; tss += sh[i + 8]; }
        sh[32] = ts; sh[33] = tss;
    }
    __syncthreads();
    float mean = sh[32] * (1.f / 16384.f);
    float var  = sh[33] * (1.f / 16384.f) - mean * mean;
    float rstd = rsqrtf(var + 1e-5f);
    if (threadIdx.x < 16) {
        int b = bg >> 5, g = bg & 31, c = g * 16 + threadIdx.x;
        float sc = gns[c] * rstd;
        ga[b * Cc + c] = sc;
        gb[b * Cc + c] = gnb[c] - mean * sc;
    }
}

// ---------------- stage 3: normalize + convert to bf16 ----------------
__global__ void gn_apply_kernel(const float* __restrict__ x, const float* __restrict__ ga,
                                const float* __restrict__ gb, bf16* __restrict__ xn) {
    size_t i = (size_t)blockIdx.x * 256 + threadIdx.x;  // float4 index
    float4 v = reinterpret_cast<const float4*>(x)[i];
    int bc = (int)(i >> 8);  // (i*4)/1024
    float a = ga[bc], b = gb[bc];
    bf162* o = reinterpret_cast<bf162*>(xn) + i * 2;
    o[0] = __floats2bfloat162_rn(v.x * a + b, v.y * a + b);
    o[1] = __floats2bfloat162_rn(v.z * a + b, v.w * a + b);
}

// ---------------- generic bf16 GEMM: C[M,N] = A[M,K] @ B[K,N] ----------------
// EPI: 0 = bf16 out + fp32 bias[row], 1 = fp32 out, 2 = bf16 out (no bias)
#define BM 128
#define BN 128
#define BK 32
#define APAD 8
#define BPAD 8

template <int EPI>
__global__ __launch_bounds__(256) void gemm_kernel(
        const bf16* __restrict__ A, const bf16* __restrict__ B, void* __restrict__ C,
        const float* __restrict__ bias, int M, int N, int K,
        long sA, long sB, long sC) {
    __shared__ bf16 As[2][BM][BK + APAD];
    __shared__ bf16 Bs[2][BK][BN + BPAD];

    int bz = blockIdx.z;
    A += (size_t)bz * sA;
    B += (size_t)bz * sB;
    int m0 = blockIdx.y * BM, n0 = blockIdx.x * BN;
    int tid = threadIdx.x, lane = tid & 31, wid = tid >> 5;
    int wm = wid & 1, wn = wid >> 1;  // 2x4 warps -> warp tile 64x32

    float acc[4][4][4];
    #pragma unroll
    for (int i = 0; i < 4; ++i)
        #pragma unroll
        for (int j = 0; j < 4; ++j)
            #pragma unroll
            for (int k = 0; k < 4; ++k) acc[i][j][k] = 0.f;

    int arow = tid >> 2, acol = (tid & 3) * 8;   // A tile: 128x32
    int brow = tid >> 4, bcol = (tid & 15) * 8;  // B tile: 32x128

    auto load_tile = [&](int kt, int buf) {
        const bf16* Ag = A + (size_t)(m0 + arow) * K + kt * BK + acol;
        cp_async16(smem_u32(&As[buf][arow][acol]), Ag);
        cp_async16(smem_u32(&As[buf][arow + 64][acol]), Ag + (size_t)64 * K);
        const bf16* Bg = B + (size_t)(kt * BK + brow) * N + n0 + bcol;
        cp_async16(smem_u32(&Bs[buf][brow][bcol]), Bg);
        cp_async16(smem_u32(&Bs[buf][brow + 16][bcol]), Bg + (size_t)16 * N);
    };

    int KT = K / BK;
    load_tile(0, 0);
    cp_commit();

    for (int kt = 0; kt < KT; ++kt) {
        int buf = kt & 1;
        cp_wait0();
        __syncthreads();
        if (kt + 1 < KT) { load_tile(kt + 1, buf ^ 1); cp_commit(); }

        #pragma unroll
        for (int ks = 0; ks < 2; ++ks) {
            uint32_t ar[4][4], br[2][4];
            #pragma unroll
            for (int mt = 0; mt < 4; ++mt)
                ldsm_x4(ar[mt], smem_u32(&As[buf][wm * 64 + mt * 16 + (lane & 15)]
                                            [ks * 16 + (lane >> 4) * 8]));
            #pragma unroll
            for (int nt2 = 0; nt2 < 2; ++nt2)
                ldsm_x4_t(br[nt2], smem_u32(&Bs[buf][ks * 16 + ((lane >> 3) & 1) * 8 + (lane & 7)]
                                               [wn * 32 + nt2 * 16 + (lane >> 4) * 8]));
            #pragma unroll
            for (int mt = 0; mt < 4; ++mt)
                #pragma unroll
                for (int nt = 0; nt < 4; ++nt)
                    mma_16816(acc[mt][nt], ar[mt], &br[nt >> 1][(nt & 1) * 2]);
        }
        __syncthreads();
    }

    int g = lane >> 2, tc = lane & 3;
    #pragma unroll
    for (int mt = 0; mt < 4; ++mt) {
        int row = m0 + wm * 64 + mt * 16 + g;
        #pragma unroll
        for (int nt = 0; nt < 4; ++nt) {
            int col = n0 + wn * 32 + nt * 8 + tc * 2;
            float* a4 = acc[mt][nt];
            if constexpr (EPI == 1) {
                float* Cp = (float*)C + (size_t)bz * sC;
                *(float2*)&Cp[(size_t)row * N + col]       = make_float2(a4[0], a4[1]);
                *(float2*)&Cp[(size_t)(row + 8) * N + col] = make_float2(a4[2], a4[3]);
            } else {
                float bv0 = 0.f, bv1 = 0.f;
                if constexpr (EPI == 0) { bv0 = bias[row]; bv1 = bias[row + 8]; }
                bf16* Cp = (bf16*)C + (size_t)bz * sC;
                *(bf162*)&Cp[(size_t)row * N + col] =
                    __floats2bfloat162_rn(a4[0] + bv0, a4[1] + bv0);
                *(bf162*)&Cp[(size_t)(row + 8) * N + col] =
                    __floats2bfloat162_rn(a4[2] + bv1, a4[3] + bv1);
            }
        }
    }
}

// ---------------- stage 5: transpose q and v: [C,N] -> [N,C] ----------------
__global__ void transpose_qv_kernel(const bf16* __restrict__ qkv,
                                    bf16* __restrict__ qt, bf16* __restrict__ vt) {
    __shared__ bf16 t[32][33];
    int z = blockIdx.z, b = z >> 1, sel = z & 1;
    const bf16* src = qkv + (size_t)b * C3 * Nn + (sel ? (size_t)2 * Cc * Nn : 0);
    bf16* dst = (sel ? vt : qt) + (size_t)b * Nn * Cc;
    int n = blockIdx.x * 32 + threadIdx.x;
    int c0 = blockIdx.y * 32;
    #pragma unroll
    for (int j = 0; j < 4; ++j)
        t[threadIdx.y + 8 * j][threadIdx.x] = src[(size_t)(c0 + threadIdx.y + 8 * j) * Nn + n];
    __syncthreads();
    int nn = blockIdx.x * 32 + threadIdx.y;
    int cc = c0 + threadIdx.x;
    #pragma unroll
    for (int j = 0; j < 4; ++j)
        dst[(size_t)(nn + 8 * j) * Cc + cc] = t[threadIdx.x][threadIdx.y + 8 * j];
}

// ---------------- stage 7: row softmax with scale, fp32 -> bf16 ----------------
__global__ __launch_bounds__(256) void softmax_kernel(const float* __restrict__ S,
                                                      bf16* __restrict__ P) {
    size_t r = blockIdx.x;
    float4 v = reinterpret_cast<const float4*>(S + r * Nn)[threadIdx.x];
    const float sc = 0.04419417382415922f;  // 512^-0.5
    v.x *= sc; v.y *= sc; v.z *= sc; v.w *= sc;
    __shared__ float sh[8];
    __shared__ float bmax, bsum;
    float m = fmaxf(fmaxf(v.x, v.y), fmaxf(v.z, v.w));
    #pragma unroll
    for (int o = 16; o > 0; o >>= 1) m = fmaxf(m, __shfl_xor_sync(~0u, m, o));
    if ((threadIdx.x & 31) == 0) sh[threadIdx.x >> 5] = m;
    __syncthreads();
    if (threadIdx.x == 0) {
        float mm = sh[0];
        #pragma unroll
        for (int i = 1; i < 8; ++i) mm = fmaxf(mm, sh[i]);
        bmax = mm;
    }
    __syncthreads();
    m = bmax;
    float4 e;
    e.x = __expf(v.x - m); e.y = __expf(v.y - m);
    e.z = __expf(v.z - m); e.w = __expf(v.w - m);
    float s = e.x + e.y + e.z + e.w;
    #pragma unroll
    for (int o = 16; o > 0; o >>= 1) s += __shfl_xor_sync(~0u, s, o);
    if ((threadIdx.x & 31) == 0) sh[threadIdx.x >> 5] = s;
    __syncthreads();
    if (threadIdx.x == 0) {
        float t = 0.f;
        #pragma unroll
        for (int i = 0; i < 8; ++i) t += sh[i];
        bsum = t;
    }
    __syncthreads();
    float inv = 1.f / bsum;
    bf162* o2 = reinterpret_cast<bf162*>(P + r * Nn) + threadIdx.x * 2;
    o2[0] = __floats2bfloat162_rn(e.x * inv, e.y * inv);
    o2[1] = __floats2bfloat162_rn(e.z * inv, e.w * inv);
}

// ---------------- stage 10: transpose outT + residual + bias ----------------
__global__ void finalize_kernel(const float* __restrict__ oT, const float* __restrict__ x,
                                const float* __restrict__ b2, float* __restrict__ out) {
    __shared__ float t[32][33];
    int b = blockIdx.z;
    const float* src = oT + (size_t)b * Nn * Cc;  // [n][o]
    const float* xb  = x + (size_t)b * Cc * Nn;   // [o][n]
    float* ob = out + (size_t)b * Cc * Nn;
    int nx = threadIdx.x;
    #pragma unroll
    for (int j = 0; j < 4; ++j) {
        int ny = threadIdx.y + 8 * j;
        t[ny][nx] = src[(size_t)(blockIdx.x * 32 + ny) * Cc + blockIdx.y * 32 + nx];
    }
    __syncthreads();
    #pragma unroll
    for (int j = 0; j < 4; ++j) {
        int oy = threadIdx.y + 8 * j;
        int orow = blockIdx.y * 32 + oy;
        size_t idx = (size_t)orow * Nn + blockIdx.x * 32 + threadIdx.x;
        ob[idx] = t[threadIdx.x][oy] + xb[idx] + b2[orow];
    }
}

// ---------------- host launcher ----------------
extern "C" void kernel_launch(void* const* d_in, const int* in_sizes, int n_in,
                              void* d_out, int out_size) {
    (void)in_sizes; (void)n_in; (void)out_size;
    const float* x   = (const float*)d_in[0];
    const float* gns = (const float*)d_in[1];
    const float* gnb = (const float*)d_in[2];
    const float* w1  = (const float*)d_in[3];
    const float* b1  = (const float*)d_in[4];
    const float* w2  = (const float*)d_in[5];
    const float* b2  = (const float*)d_in[6];
    float* out = (float*)d_out;

    void *pga, *pgb, *pw1, *pw2t, *pxn, *pqkv, *pqt, *pvt, *pS, *pP, *pattn, *poT;
    cudaGetSymbolAddress(&pga, g_ga);
    cudaGetSymbolAddress(&pgb, g_gb);
    cudaGetSymbolAddress(&pw1, g_w1b);
    cudaGetSymbolAddress(&pw2t, g_w2t);
    cudaGetSymbolAddress(&pxn, g_xn);
    cudaGetSymbolAddress(&pqkv, g_qkv);
    cudaGetSymbolAddress(&pqt, g_qt);
    cudaGetSymbolAddress(&pvt, g_vt);
    cudaGetSymbolAddress(&pS, g_S);
    cudaGetSymbolAddress(&pP, g_P);
    cudaGetSymbolAddress(&pattn, g_attn);
    cudaGetSymbolAddress(&poT, g_oT);

    // 1) weights -> bf16 (w2 transposed)
    wconv_kernel<<<3072, 256>>>(w1, w2, (bf16*)pw1, (bf16*)pw2t);
    // 2) groupnorm stats
    gn_stats_kernel<<<Bb * 32, 256>>>(x, gns, gnb, (float*)pga, (float*)pgb);
    // 3) normalize + bf16
    gn_apply_kernel<<<16384, 256>>>(x, (float*)pga, (float*)pgb, (bf16*)pxn);
    // 4) QKV GEMM: [1536,512] x [512,1024] per batch, +b1
    gemm_kernel<0><<<dim3(8, 12, Bb), 256>>>((const bf16*)pw1, (const bf16*)pxn, pqkv,
                                             b1, C3, Nn, Cc,
                                             0L, (long)Cc * Nn, (long)C3 * Nn);
    // 5) transpose q, v -> [N,C]
    transpose_qv_kernel<<<dim3(32, 16, 2 * Bb), dim3(32, 8)>>>((const bf16*)pqkv,
                                                               (bf16*)pqt, (bf16*)pvt);
    // 6) S = qT @ k : [1024,512] x [512,1024], fp32 out
    gemm_kernel<1><<<dim3(8, 8, Bb), 256>>>((const bf16*)pqt,
                                            (const bf16*)pqkv + (size_t)Cc * Nn, pS,
                                            nullptr, Nn, Nn, Cc,
                                            (long)Nn * Cc, (long)C3 * Nn, (long)Nn * Nn);
    // 7) softmax rows -> bf16 P
    softmax_kernel<<<Bb * Nn, 256>>>((const float*)pS, (bf16*)pP);
    // 8) attn = P @ vT : [1024,1024] x [1024,512], bf16 out
    gemm_kernel<2><<<dim3(4, 8, Bb), 256>>>((const bf16*)pP, (const bf16*)pvt, pattn,
                                            nullptr, Nn, Cc, Nn,
                                            (long)Nn * Nn, (long)Nn * Cc, (long)Nn * Cc);
    // 9) outT = attn @ w2t : [1024,512] x [512,512], fp32 out
    gemm_kernel<1><<<dim3(4, 8, Bb), 256>>>((const bf16*)pattn, (const bf16*)pw2t, poT,
                                            nullptr, Nn, Cc, Cc,
                                            (long)Nn * Cc, 0L, (long)Nn * Cc);
    // 10) transpose + residual + b2 -> d_out
    finalize_kernel<<<dim3(32, 16, Bb), dim3(32, 8)>>>((const float*)poT, x, b2, out);
}

// round 4
// speedup vs baseline: 1.0343x; 1.0343x over previous
#include <cuda_runtime.h>
#include <cuda_bf16.h>
#include <cstdint>

using bf16  = __nv_bfloat16;
using bf162 = __nv_bfloat162;

static constexpr int Bb = 32, Cc = 512, Nn = 1024, C3 = 1536;

// ---------------- device scratch ----------------
__device__ __align__(16) float g_ga[Bb * Cc];
__device__ __align__(16) float g_gb[Bb * Cc];
__device__ __align__(16) bf16  g_w1b[C3 * Cc];
__device__ __align__(16) bf16  g_w2b[Cc * Cc];
__device__ __align__(16) bf16  g_xnT [(size_t)Bb * Nn * Cc];
__device__ __align__(16) bf16  g_qkv [(size_t)Bb * C3 * Nn];
__device__ __align__(16) bf16  g_qt  [(size_t)Bb * Nn * Cc];
__device__ __align__(16) bf16  g_kt  [(size_t)Bb * Nn * Cc];
__device__ __align__(16) float g_S   [(size_t)Bb * Nn * Nn];
__device__ __align__(16) bf16  g_P   [(size_t)Bb * Nn * Nn];
__device__ __align__(16) bf16  g_attn[(size_t)Bb * Nn * Cc];

// ---------------- PTX helpers ----------------
__device__ __forceinline__ uint32_t smem_u32(const void* p) {
    return (uint32_t)__cvta_generic_to_shared(p);
}
__device__ __forceinline__ void cp_async16(uint32_t s, const void* g) {
    asm volatile("cp.async.cg.shared.global [%0], [%1], 16;\n" :: "r"(s), "l"(g));
}
__device__ __forceinline__ void cp_commit() {
    asm volatile("cp.async.commit_group;\n" ::: "memory");
}
template <int N>
__device__ __forceinline__ void cp_wait() {
    asm volatile("cp.async.wait_group %0;\n" :: "n"(N) : "memory");
}
__device__ __forceinline__ void ldsm_x4(uint32_t* r, uint32_t addr) {
    asm volatile("ldmatrix.sync.aligned.m8n8.x4.shared.b16 {%0,%1,%2,%3}, [%4];\n"
                 : "=r"(r[0]), "=r"(r[1]), "=r"(r[2]), "=r"(r[3]) : "r"(addr));
}
__device__ __forceinline__ void mma_16816(float* d, const uint32_t* a,
                                          uint32_t b0, uint32_t b1) {
    asm volatile("mma.sync.aligned.m16n8k16.row.col.f32.bf16.bf16.f32 "
                 "{%0,%1,%2,%3}, {%4,%5,%6,%7}, {%8,%9}, {%0,%1,%2,%3};\n"
                 : "+f"(d[0]), "+f"(d[1]), "+f"(d[2]), "+f"(d[3])
                 : "r"(a[0]), "r"(a[1]), "r"(a[2]), "r"(a[3]), "r"(b0), "r"(b1));
}

// ---------------- mma.sync GEMM: D[M,N] = A[M,K] @ B[N,K]^T ----------------
// Both operands K-major. tile 128x128, BK=64, 3 stages, 256 threads.
// EPI: 0 = bf16 + bias[row], 1 = f32, 2 = bf16, 3 = f32 + bias[row] + resid
static constexpr int BM = 128, BN = 128, BK = 64, PAD = 8, NST = 3;
static constexpr int LDT = BK + PAD;                 // 72 halves per row
static constexpr int SAe = BM * LDT;                 // elems per stage per operand
static constexpr int GSMEM = 2 * NST * SAe * 2;      // bytes (A + B, 3 stages)

template <int EPI>
__global__ __launch_bounds__(256) void gemm_bt(
        const bf16* __restrict__ A, const bf16* __restrict__ B, void* __restrict__ C,
        const float* __restrict__ bias, const float* __restrict__ resid,
        int M, int N, int K, int ldA, int ldB, int ldC,
        long sA, long sB, long sC, long sR) {
    extern __shared__ bf16 sm[];
    bf16* AsAll = sm;
    bf16* BsAll = sm + NST * SAe;

    const int tid = threadIdx.x, lane = tid & 31, wid = tid >> 5;
    const int wm = wid & 1, wn = wid >> 1;  // 2x4 warps, warp tile 64x32
    const int m0 = blockIdx.y * BM, n0 = blockIdx.x * BN, bz = blockIdx.z;
    A += (size_t)bz * sA;
    B += (size_t)bz * sB;

    float acc[4][4][4];
    #pragma unroll
    for (int i = 0; i < 4; ++i)
        #pragma unroll
        for (int j = 0; j < 4; ++j)
            #pragma unroll
            for (int k = 0; k < 4; ++k) acc[i][j][k] = 0.f;

    const int lr = tid >> 3, lc = (tid & 7) * 8;  // 16B chunks: 32 rows x 8 chunks/row

    auto load_stage = [&](int kt, int s) {
        bf16* As = AsAll + s * SAe;
        bf16* Bs = BsAll + s * SAe;
        const bf16* Ag = A + (size_t)m0 * ldA + kt * BK;
        const bf16* Bg = B + (size_t)n0 * ldB + kt * BK;
        #pragma unroll
        for (int i = 0; i < 4; ++i) {
            int r = lr + i * 32;
            cp_async16(smem_u32(As + r * LDT + lc), Ag + (size_t)r * ldA + lc);
        }
        #pragma unroll
        for (int i = 0; i < 4; ++i) {
            int r = lr + i * 32;
            cp_async16(smem_u32(Bs + r * LDT + lc), Bg + (size_t)r * ldB + lc);
        }
        cp_commit();
    };

    const int KT = K / BK;
    load_stage(0, 0);
    load_stage(1, 1);

    int sIdx = 0;
    for (int kt = 0; kt < KT; ++kt) {
        if (kt == KT - 1) cp_wait<0>(); else cp_wait<1>();
        __syncthreads();
        if (kt + 2 < KT) {
            int ns = sIdx + 2; if (ns >= NST) ns -= NST;
            load_stage(kt + 2, ns);
        }

        const bf16* As = AsAll + sIdx * SAe;
        const bf16* Bs = BsAll + sIdx * SAe;
        // ldmatrix base addresses (non-trans for BOTH operands; K-major tiles)
        uint32_t aAddr = smem_u32(As + (wm * 64 + (lane & 15)) * LDT + (lane >> 4) * 8);
        uint32_t bAddr = smem_u32(Bs + (wn * 32 + (lane & 15)) * LDT + (lane >> 4) * 8);

        #pragma unroll
        for (int ks = 0; ks < 4; ++ks) {
            uint32_t ar[4][4], br[2][4];
            #pragma unroll
            for (int mt = 0; mt < 4; ++mt)
                ldsm_x4(ar[mt], aAddr + (uint32_t)(mt * 16 * LDT + ks * 16) * 2);
            #pragma unroll
            for (int rg = 0; rg < 2; ++rg)
                ldsm_x4(br[rg], bAddr + (uint32_t)(rg * 16 * LDT + ks * 16) * 2);
            #pragma unroll
            for (int mt = 0; mt < 4; ++mt)
                #pragma unroll
                for (int nt = 0; nt < 4; ++nt)
                    mma_16816(acc[mt][nt], ar[mt],
                              br[nt >> 1][nt & 1], br[nt >> 1][(nt & 1) + 2]);
        }
        ++sIdx; if (sIdx >= NST) sIdx = 0;
    }

    // epilogue
    const int g = lane >> 2, tc = lane & 3;
    #pragma unroll
    for (int mt = 0; mt < 4; ++mt) {
        int row = m0 + wm * 64 + mt * 16 + g;
        float bv0 = 0.f, bv1 = 0.f;
        if constexpr (EPI == 0 || EPI == 3) { bv0 = bias[row]; bv1 = bias[row + 8]; }
        #pragma unroll
        for (int nt = 0; nt < 4; ++nt) {
            int col = n0 + wn * 32 + nt * 8 + tc * 2;
            float* a4 = acc[mt][nt];
            if constexpr (EPI == 1 || EPI == 3) {
                float* Cp = (float*)C + (size_t)bz * sC;
                float2 v0 = make_float2(a4[0], a4[1]);
                float2 v1 = make_float2(a4[2], a4[3]);
                if constexpr (EPI == 3) {
                    const float* Rp = resid + (size_t)bz * sR;
                    float2 x0 = *(const float2*)&Rp[(size_t)row * ldC + col];
                    float2 x1 = *(const float2*)&Rp[(size_t)(row + 8) * ldC + col];
                    v0.x += bv0 + x0.x; v0.y += bv0 + x0.y;
                    v1.x += bv1 + x1.x; v1.y += bv1 + x1.y;
                }
                *(float2*)&Cp[(size_t)row * ldC + col]       = v0;
                *(float2*)&Cp[(size_t)(row + 8) * ldC + col] = v1;
            } else {
                bf16* Cp = (bf16*)C + (size_t)bz * sC;
                *(bf162*)&Cp[(size_t)row * ldC + col] =
                    __floats2bfloat162_rn(a4[0] + bv0, a4[1] + bv0);
                *(bf162*)&Cp[(size_t)(row + 8) * ldC + col] =
                    __floats2bfloat162_rn(a4[2] + bv1, a4[3] + bv1);
            }
        }
    }
}

// ---------------- stage 1: weight convert ----------------
__global__ void wconv_kernel(const float* __restrict__ w1, const float* __restrict__ w2,
                             bf16* __restrict__ w1b, bf16* __restrict__ w2b) {
    int i = blockIdx.x * 256 + threadIdx.x;
    if (i < C3 * Cc) w1b[i] = __float2bfloat16(w1[i]);
    if (i < Cc * Cc) w2b[i] = __float2bfloat16(w2[i]);
}

// ---------------- stage 2: groupnorm stats ----------------
__global__ __launch_bounds__(256) void gn_stats_kernel(
        const float* __restrict__ x, const float* __restrict__ gns,
        const float* __restrict__ gnb, float* __restrict__ ga, float* __restrict__ gb) {
    int bg = blockIdx.x;
    const float4* p = reinterpret_cast<const float4*>(x) + (size_t)bg * 4096;
    float s = 0.f, ss = 0.f;
    for (int i = threadIdx.x; i < 4096; i += 256) {
        float4 v = p[i];
        s  += v.x + v.y + v.z + v.w;
        ss += v.x * v.x + v.y * v.y + v.z * v.z + v.w * v.w;
    }
    __shared__ float sh[34];
    #pragma unroll
    for (int o = 16; o > 0; o >>= 1) {
        s  += __shfl_xor_sync(~0u, s, o);
        ss += __shfl_xor_sync(~0u, ss, o);
    }
    int w = threadIdx.x >> 5;
    if ((threadIdx.x & 31) == 0) { sh[w] = s; sh[w + 8] = ss; }
    __syncthreads();
    if (threadIdx.x == 0) {
        float ts = 0.f, tss = 0.f;
        #pragma unroll
        for (int i = 0; i < 8; ++i) { ts += sh[i]; tss += sh[i + 8]; }
        sh[32] = ts; sh[33] = tss;
    }
    __syncthreads();
    float mean = sh[32] * (1.f / 16384.f);
    float var  = sh[33] * (1.f / 16384.f) - mean * mean;
    float rstd = rsqrtf(var + 1e-5f);
    if (threadIdx.x < 16) {
        int b = bg >> 5, gI = bg & 31, c = gI * 16 + threadIdx.x;
        float sc = gns[c] * rstd;
        ga[b * Cc + c] = sc;
        gb[b * Cc + c] = gnb[c] - mean * sc;
    }
}

// ---------------- stage 3: normalize + transpose -> xnT[b][n][c] ----------------
__global__ void gn_apply_t_kernel(const float* __restrict__ x, const float* __restrict__ ga,
                                  const float* __restrict__ gb, bf16* __restrict__ xnT) {
    __shared__ float t[32][33];
    int b = blockIdx.z;
    const float* xb = x + (size_t)b * Cc * Nn;
    int n0 = blockIdx.x * 32, c0 = blockIdx.y * 32;
    #pragma unroll
    for (int j = 0; j < 4; ++j) {
        int c = c0 + threadIdx.y + 8 * j;
        float v = xb[(size_t)c * Nn + n0 + threadIdx.x];
        t[threadIdx.y + 8 * j][threadIdx.x] = v * ga[b * Cc + c] + gb[b * Cc + c];
    }
    __syncthreads();
    bf16* ob = xnT + (size_t)b * Nn * Cc;
    #pragma unroll
    for (int j = 0; j < 4; ++j) {
        int n = n0 + threadIdx.y + 8 * j;
        ob[(size_t)n * Cc + c0 + threadIdx.x] =
            __float2bfloat16(t[threadIdx.x][threadIdx.y + 8 * j]);
    }
}

// ---------------- stage 5: transpose q,k: qkv[o,n] -> qt/kt[n,c] ----------------
__global__ void transpose_qk_kernel(const bf16* __restrict__ qkv,
                                    bf16* __restrict__ qt, bf16* __restrict__ kt) {
    __shared__ bf16 t[32][33];
    int z = blockIdx.z, b = z >> 1, sel = z & 1;
    const bf16* src = qkv + (size_t)b * C3 * Nn + (size_t)sel * Cc * Nn;
    bf16* dst = (sel ? kt : qt) + (size_t)b * Nn * Cc;
    int n = blockIdx.x * 32 + threadIdx.x;
    int c0 = blockIdx.y * 32;
    #pragma unroll
    for (int j = 0; j < 4; ++j)
        t[threadIdx.y + 8 * j][threadIdx.x] = src[(size_t)(c0 + threadIdx.y + 8 * j) * Nn + n];
    __syncthreads();
    int nn = blockIdx.x * 32 + threadIdx.y;
    int cc = c0 + threadIdx.x;
    #pragma unroll
    for (int j = 0; j < 4; ++j)
        dst[(size_t)(nn + 8 * j) * Cc + cc] = t[threadIdx.x][threadIdx.y + 8 * j];
}

// ---------------- stage 7: softmax rows fp32 -> bf16 ----------------
__global__ __launch_bounds__(256) void softmax_kernel(const float* __restrict__ S,
                                                      bf16* __restrict__ P) {
    size_t r = blockIdx.x;
    float4 v = reinterpret_cast<const float4*>(S + r * Nn)[threadIdx.x];
    const float sc = 0.04419417382415922f;  // 512^-0.5
    v.x *= sc; v.y *= sc; v.z *= sc; v.w *= sc;
    __shared__ float sh[8];
    __shared__ float bmax, bsum;
    float m = fmaxf(fmaxf(v.x, v.y), fmaxf(v.z, v.w));
    #pragma unroll
    for (int o = 16; o > 0; o >>= 1) m = fmaxf(m, __shfl_xor_sync(~0u, m, o));
    if ((threadIdx.x & 31) == 0) sh[threadIdx.x >> 5] = m;
    __syncthreads();
    if (threadIdx.x == 0) {
        float mm = sh[0];
        #pragma unroll
        for (int i = 1; i < 8; ++i) mm = fmaxf(mm, sh[i]);
        bmax = mm;
    }
    __syncthreads();
    m = bmax;
    float4 e;
    e.x = __expf(v.x - m); e.y = __expf(v.y - m);
    e.z = __expf(v.z - m); e.w = __expf(v.w - m);
    float s = e.x + e.y + e.z + e.w;
    #pragma unroll
    for (int o = 16; o > 0; o >>= 1) s += __shfl_xor_sync(~0u, s, o);
    if ((threadIdx.x & 31) == 0) sh[threadIdx.x >> 5] = s;
    __syncthreads();
    if (threadIdx.x == 0) {
        float t = 0.f;
        #pragma unroll
        for (int i = 0; i < 8; ++i) t += sh[i];
        bsum = t;
    }
    __syncthreads();
    float inv = 1.f / bsum;
    bf162* o2 = reinterpret_cast<bf162*>(P + r * Nn) + threadIdx.x * 2;
    o2[0] = __floats2bfloat162_rn(e.x * inv, e.y * inv);
    o2[1] = __floats2bfloat162_rn(e.z * inv, e.w * inv);
}

// ---------------- host launcher ----------------
extern "C" void kernel_launch(void* const* d_in, const int* in_sizes, int n_in,
                              void* d_out, int out_size) {
    (void)in_sizes; (void)n_in; (void)out_size;
    const float* x   = (const float*)d_in[0];
    const float* gns = (const float*)d_in[1];
    const float* gnb = (const float*)d_in[2];
    const float* w1  = (const float*)d_in[3];
    const float* b1  = (const float*)d_in[4];
    const float* w2  = (const float*)d_in[5];
    const float* b2  = (const float*)d_in[6];
    float* out = (float*)d_out;

    void *pga, *pgb, *pw1, *pw2, *pxn, *pqkv, *pqt, *pkt, *pS, *pP, *pattn;
    cudaGetSymbolAddress(&pga, g_ga);
    cudaGetSymbolAddress(&pgb, g_gb);
    cudaGetSymbolAddress(&pw1, g_w1b);
    cudaGetSymbolAddress(&pw2, g_w2b);
    cudaGetSymbolAddress(&pxn, g_xnT);
    cudaGetSymbolAddress(&pqkv, g_qkv);
    cudaGetSymbolAddress(&pqt, g_qt);
    cudaGetSymbolAddress(&pkt, g_kt);
    cudaGetSymbolAddress(&pS, g_S);
    cudaGetSymbolAddress(&pP, g_P);
    cudaGetSymbolAddress(&pattn, g_attn);

    cudaFuncSetAttribute(gemm_bt<0>, cudaFuncAttributeMaxDynamicSharedMemorySize, GSMEM);
    cudaFuncSetAttribute(gemm_bt<1>, cudaFuncAttributeMaxDynamicSharedMemorySize, GSMEM);
    cudaFuncSetAttribute(gemm_bt<2>, cudaFuncAttributeMaxDynamicSharedMemorySize, GSMEM);
    cudaFuncSetAttribute(gemm_bt<3>, cudaFuncAttributeMaxDynamicSharedMemorySize, GSMEM);

    // 1) weights -> bf16
    wconv_kernel<<<3072, 256>>>(w1, w2, (bf16*)pw1, (bf16*)pw2);
    // 2) groupnorm stats
    gn_stats_kernel<<<Bb * 32, 256>>>(x, gns, gnb, (float*)pga, (float*)pgb);
    // 3) normalize + transpose -> xnT [b,n,c]
    gn_apply_t_kernel<<<dim3(32, 16, Bb), dim3(32, 8)>>>(x, (float*)pga, (float*)pgb,
                                                         (bf16*)pxn);
    // 4) QKV: qkv[o,n] = w1[o,:] . xnT[n,:] + b1[o]
    gemm_bt<0><<<dim3(8, 12, Bb), 256, GSMEM>>>(
        (const bf16*)pw1, (const bf16*)pxn, pqkv, b1, nullptr,
        C3, Nn, Cc, Cc, Cc, Nn, 0L, (long)Nn * Cc, (long)C3 * Nn, 0L);
    // 5) transpose q,k -> [n,c]
    transpose_qk_kernel<<<dim3(32, 16, 2 * Bb), dim3(32, 8)>>>((const bf16*)pqkv,
                                                               (bf16*)pqt, (bf16*)pkt);
    // 6) S[n,m] = qt[n,:] . kt[m,:]  (fp32)
    gemm_bt<1><<<dim3(8, 8, Bb), 256, GSMEM>>>(
        (const bf16*)pqt, (const bf16*)pkt, pS, nullptr, nullptr,
        Nn, Nn, Cc, Cc, Cc, Nn, (long)Nn * Cc, (long)Nn * Cc, (long)Nn * Nn, 0L);
    // 7) softmax -> P bf16
    softmax_kernel<<<Bb * Nn, 256>>>((const float*)pS, (bf16*)pP);
    // 8) attn[n,c] = P[n,:] . v[c,:]   (v rows of qkv, [c,m] K-major)
    gemm_bt<2><<<dim3(4, 8, Bb), 256, GSMEM>>>(
        (const bf16*)pP, (const bf16*)pqkv + (size_t)2 * Cc * Nn, pattn, nullptr, nullptr,
        Nn, Cc, Nn, Nn, Nn, Cc, (long)Nn * Nn, (long)C3 * Nn, (long)Nn * Cc, 0L);
    // 9) out[o,n] = w2[o,:] . attn[n,:] + b2[o] + x[o,n]  (fused residual)
    gemm_bt<3><<<dim3(8, 4, Bb), 256, GSMEM>>>(
        (const bf16*)pw2, (const bf16*)pattn, out, b2, x,
        Cc, Nn, Cc, Cc, Cc, Nn, 0L, (long)Nn * Cc, (long)Cc * Nn, (long)Cc * Nn);
}